// round 8
// baseline (speedup 1.0000x reference)
#include <cuda_runtime.h>
#include <math.h>

// ---- problem constants: B=64, W=128, C=20, D=256, H=512, G=2048 ----
// NW = 8192 words, NC = 163840 char positions.

// ---------------- device scratch (no allocations allowed) ----------------
__device__ float g_cat[163840 * 512];        // [NC][512]
__device__ float g_scorep[163840 * 4];       // [NC][4] partial score sums
__device__ float g_we[8192 * 512];           // [NW][512]
__device__ float g_feats[8192 * 512];        // [t][b][512]
__device__ float g_xg0[2 * 8192 * 2048];     // [dir][t*64+b][2048]
__device__ float g_xg1[2 * 8192 * 2048];
__device__ float g_h0[128 * 64 * 1024];      // [t][b][dir*512+e]
__device__ float g_h1[128 * 64 * 1024];
__device__ float g_cst[2 * 64 * 512];        // cell state per dir
__device__ float g_gates[2 * 64 * 2048];     // per-step gate buffer
__device__ float g_Wcat[512 * 768];          // packed conv weights (NT)
__device__ float g_bcat[512];
__device__ float g_WaT[512 * 512];           // Wa transposed (NT)
__device__ float g_W1T[256 * 512];           // W1 transposed (NT)
__device__ float g_pe[20 * 256];             // positional encoding

__device__ __forceinline__ float sigm(float x) { return 1.0f / (1.0f + expf(-x)); }

// ---------------- prep kernels ----------------
__global__ void prep_wcat_k(const float* __restrict__ wbi, const float* __restrict__ bbi,
                            const float* __restrict__ wtri, const float* __restrict__ btri) {
    int o = blockIdx.x;  // 0..511
    for (int k = threadIdx.x; k < 768; k += 256) {
        int grp = k >> 8, i = k & 255;
        float v;
        if (o < 256) v = (grp < 2) ? wbi[(o * 256 + i) * 2 + grp] : 0.0f;
        else         v = wtri[((o - 256) * 256 + i) * 3 + grp];
        g_Wcat[o * 768 + k] = v;
    }
    if (threadIdx.x == 0) g_bcat[o] = (o < 256) ? bbi[o] : btri[o - 256];
}

__global__ void prep_misc_k(const float* __restrict__ Wa, const float* __restrict__ W1) {
    int e = blockIdx.x;  // 0..511
    for (int d = threadIdx.x; d < 512; d += 256)
        g_WaT[e * 512 + d] = Wa[d * 512 + e];
    if (e < 256)
        for (int d = threadIdx.x; d < 512; d += 256)
            g_W1T[e * 512 + d] = W1[d * 256 + e];
    if (e < 20) {
        int o = threadIdx.x;  // 0..255
        int p = o >> 1;
        float ang = (float)e * expf(-(float)(2 * p) * (logf(10000.0f) / 256.0f));
        g_pe[e * 256 + o] = (o & 1) ? cosf(ang) : sinf(ang);
    }
}

// ---------------- generic NT SGEMM, 128x128 tile, 256 threads, 8x8 micro ----
// C[M,N] = A[M,K] @ B[N,K]^T  (+ epilogue)
// AMODE 0: row-major A (lda).  AMODE 1: char-table gather (K=768).
// EMODE 0: C = acc + bias[z*sBias + col]          (z-batched via gridDim.z)
// EMODE 1: C = acc + bias[col] + pe[row%20][col&255]
// EMODE 2: scorep[row*4 + bx] = sum_col tanh(acc+bias[col])*ua[col]  (no C)
// EMODE 3: permuted rows: orow = (row&127)*64 + (row>>7)             (no bias)
template <int AMODE, int EMODE>
__global__ void __launch_bounds__(256) gemm_k(
    const float* __restrict__ A, int lda,
    const float* __restrict__ Bm, int ldb, long long sB,
    float* __restrict__ Cm, int ldc, long long sC,
    const float* __restrict__ bias, int sBias,
    int K,
    const int* __restrict__ srcI, const float* __restrict__ tbl,
    const float* __restrict__ peA, const float* __restrict__ uaV,
    float* __restrict__ scorepO) {
    __shared__ float As[16 * 132];
    __shared__ float Bs[16 * 132];

    const int z = blockIdx.z;
    const int row0 = blockIdx.y * 128;
    const int col0 = blockIdx.x * 128;
    const int tid = threadIdx.x;
    const int ty = tid >> 4, tx = tid & 15;

    const int mL = tid >> 1;          // 0..127, shared by A & B loads
    const int q0 = (tid & 1) * 2;     // k-quad base (q0, q0+1)
    const int rowL = row0 + mL;
    int tw = 0;
    if (AMODE == 1) tw = rowL % 20;
    const float* Arow = (AMODE == 0) ? (A + (size_t)rowL * lda) : (const float*)0;
    const float* Brow = Bm + (size_t)z * sB + (size_t)(col0 + mL) * ldb;

    float acc[8][8];
#pragma unroll
    for (int i = 0; i < 8; i++)
#pragma unroll
        for (int j = 0; j < 8; j++) acc[i][j] = 0.0f;

    for (int kt = 0; kt < K; kt += 16) {
        float4 av[2], bv[2];
#pragma unroll
        for (int r = 0; r < 2; r++) {
            int q = q0 + r;
            int k = kt + q * 4;
            if (AMODE == 0) {
                av[r] = *(const float4*)(Arow + k);
            } else {
                int grp = k >> 8, ii = k & 255;
                if (tw + grp < 20) {
                    int ci = srcI[rowL + grp];
                    av[r] = *(const float4*)(tbl + (size_t)ci * 256 + ii);
                } else {
                    av[r] = make_float4(0.f, 0.f, 0.f, 0.f);
                }
            }
            bv[r] = *(const float4*)(Brow + k);
        }
        __syncthreads();
#pragma unroll
        for (int r = 0; r < 2; r++) {
            int q = q0 + r;
            As[(q * 4 + 0) * 132 + mL] = av[r].x;
            As[(q * 4 + 1) * 132 + mL] = av[r].y;
            As[(q * 4 + 2) * 132 + mL] = av[r].z;
            As[(q * 4 + 3) * 132 + mL] = av[r].w;
            Bs[(q * 4 + 0) * 132 + mL] = bv[r].x;
            Bs[(q * 4 + 1) * 132 + mL] = bv[r].y;
            Bs[(q * 4 + 2) * 132 + mL] = bv[r].z;
            Bs[(q * 4 + 3) * 132 + mL] = bv[r].w;
        }
        __syncthreads();
#pragma unroll
        for (int k = 0; k < 16; k++) {
            float4 a0 = *(const float4*)&As[k * 132 + ty * 8];
            float4 a1 = *(const float4*)&As[k * 132 + ty * 8 + 4];
            float4 b0 = *(const float4*)&Bs[k * 132 + tx * 8];
            float4 b1 = *(const float4*)&Bs[k * 132 + tx * 8 + 4];
            float aa[8] = {a0.x, a0.y, a0.z, a0.w, a1.x, a1.y, a1.z, a1.w};
            float bb[8] = {b0.x, b0.y, b0.z, b0.w, b1.x, b1.y, b1.z, b1.w};
#pragma unroll
            for (int i = 0; i < 8; i++)
#pragma unroll
                for (int j = 0; j < 8; j++) acc[i][j] += aa[i] * bb[j];
        }
    }

    if constexpr (EMODE == 2) {
#pragma unroll
        for (int i = 0; i < 8; i++) {
            int row = row0 + ty * 8 + i;
            float s = 0.0f;
#pragma unroll
            for (int j = 0; j < 8; j++) {
                int col = col0 + tx * 8 + j;
                s += tanhf(acc[i][j] + bias[col]) * uaV[col];
            }
            s += __shfl_xor_sync(0xffffffffu, s, 8);
            s += __shfl_xor_sync(0xffffffffu, s, 4);
            s += __shfl_xor_sync(0xffffffffu, s, 2);
            s += __shfl_xor_sync(0xffffffffu, s, 1);
            if (tx == 0) scorepO[(size_t)row * 4 + blockIdx.x] = s;
        }
    } else {
        float* Cz = Cm + (size_t)z * sC;
#pragma unroll
        for (int i = 0; i < 8; i++) {
            int row = row0 + ty * 8 + i;
            float* crow;
            if constexpr (EMODE == 3) {
                int orow = (row & 127) * 64 + (row >> 7);
                crow = Cz + (size_t)orow * ldc;
            } else {
                crow = Cz + (size_t)row * ldc;
            }
            int trow = 0;
            if constexpr (EMODE == 1) trow = row % 20;
#pragma unroll
            for (int j = 0; j < 8; j++) {
                int col = col0 + tx * 8 + j;
                float v = acc[i][j];
                if constexpr (EMODE == 0) v += bias[(size_t)z * sBias + col];
                if constexpr (EMODE == 1) v += bias[col] + peA[trow * 256 + (col & 255)];
                crow[col] = v;
            }
        }
    }
}

// ---------------- attention: softmax over 20 chars + weighted sum ----------------
__global__ void attn_k(const float* __restrict__ cat, const float* __restrict__ scorep,
                       float* __restrict__ we) {
    int n = blockIdx.x;  // word index, 0..8191
    int tid = threadIdx.x;
    __shared__ float a[20];
    if (tid < 20) {
        const float* sp = scorep + (size_t)(n * 20 + tid) * 4;
        a[tid] = sp[0] + sp[1] + sp[2] + sp[3];
    }
    __syncthreads();
    if (tid == 0) {
        float mx = a[0];
        for (int t = 1; t < 20; t++) mx = fmaxf(mx, a[t]);
        float s = 0.0f;
        for (int t = 0; t < 20; t++) { a[t] = expf(a[t] - mx); s += a[t]; }
        float inv = 1.0f / s;
        for (int t = 0; t < 20; t++) a[t] *= inv;
    }
    __syncthreads();
    const float* cp = cat + (size_t)n * 20 * 512;
    for (int e = tid; e < 512; e += 256) {
        float acc = 0.0f;
#pragma unroll
        for (int t = 0; t < 20; t++) acc += a[t] * cp[t * 512 + e];
        we[(size_t)n * 512 + e] = acc;
    }
}

// ---------------- word table gather into feats[..][256:512] ----------------
__global__ void wgather_k(const int* __restrict__ wsrc, const float* __restrict__ wtab,
                          float* __restrict__ feats) {
    int n = blockIdx.x;  // 0..8191, n = b*128 + w
    int b = n >> 7, w = n & 127;
    int orow = w * 64 + b;
    const float4* sp = (const float4*)(wtab + (size_t)wsrc[n] * 256);
    float4* dp = (float4*)(feats + (size_t)orow * 512 + 256);
    dp[threadIdx.x] = sp[threadIdx.x];  // 64 threads x float4 = 256 floats
}

// ---------------- LSTM recurrent gates GEMM: g = xg + h_prev @ whh^T -------
// grid (64, 1, 2): 64 gate-chunks of 32, z = dir.  tile M=64 x N=32, K=512.
__global__ void __launch_bounds__(256) lstm_gates_k(
    const float* __restrict__ h, const float* __restrict__ whh,
    const float* __restrict__ xg, float* __restrict__ gates, int s) {
    __shared__ float As[16 * 68];
    __shared__ float Bs[16 * 36];
    int dir = blockIdx.z;
    int col0 = blockIdx.x * 32;
    int tid = threadIdx.x;
    int t = dir ? (127 - s) : s;
    int tprev = dir ? (128 - s) : (s - 1);
    const float* Abase = h + (size_t)tprev * 65536 + (size_t)dir * 512;
    const float* Bbase = whh + (size_t)dir * 2048 * 512 + (size_t)col0 * 512;
    int mA = tid >> 2, qA = tid & 3;
    int ty = tid >> 4, tx = tid & 15;

    float acc[4][2] = {{0.f, 0.f}, {0.f, 0.f}, {0.f, 0.f}, {0.f, 0.f}};

    if (s > 0) {
        for (int kt = 0; kt < 512; kt += 16) {
            float4 a = *(const float4*)(Abase + (size_t)mA * 1024 + kt + qA * 4);
            float4 b = make_float4(0.f, 0.f, 0.f, 0.f);
            if (tid < 128)
                b = *(const float4*)(Bbase + (size_t)(tid >> 2) * 512 + kt + (tid & 3) * 4);
            __syncthreads();
            As[(qA * 4 + 0) * 68 + mA] = a.x;
            As[(qA * 4 + 1) * 68 + mA] = a.y;
            As[(qA * 4 + 2) * 68 + mA] = a.z;
            As[(qA * 4 + 3) * 68 + mA] = a.w;
            if (tid < 128) {
                int nB = tid >> 2, qB = tid & 3;
                Bs[(qB * 4 + 0) * 36 + nB] = b.x;
                Bs[(qB * 4 + 1) * 36 + nB] = b.y;
                Bs[(qB * 4 + 2) * 36 + nB] = b.z;
                Bs[(qB * 4 + 3) * 36 + nB] = b.w;
            }
            __syncthreads();
#pragma unroll
            for (int k = 0; k < 16; k++) {
                float4 a4 = *(const float4*)&As[k * 68 + ty * 4];
                float2 b2 = *(const float2*)&Bs[k * 36 + tx * 2];
                acc[0][0] += a4.x * b2.x; acc[0][1] += a4.x * b2.y;
                acc[1][0] += a4.y * b2.x; acc[1][1] += a4.y * b2.y;
                acc[2][0] += a4.z * b2.x; acc[2][1] += a4.z * b2.y;
                acc[3][0] += a4.w * b2.x; acc[3][1] += a4.w * b2.y;
            }
        }
    }
    const float* xgp = xg + ((size_t)dir * 8192 + (size_t)t * 64) * 2048;
    float* gp = gates + (size_t)dir * 131072;
#pragma unroll
    for (int i = 0; i < 4; i++) {
        int brow = ty * 4 + i;
#pragma unroll
        for (int j = 0; j < 2; j++) {
            int g = col0 + tx * 2 + j;
            gp[(size_t)brow * 2048 + g] = acc[i][j] + xgp[(size_t)brow * 2048 + g];
        }
    }
}

// ---------------- LSTM pointwise update ----------------
__global__ void lstm_update_k(const float* __restrict__ gates, float* __restrict__ cbuf,
                              float* __restrict__ hbuf, int s) {
    int dir = blockIdx.z;
    int b = blockIdx.x;
    int tid = threadIdx.x;
    int t = dir ? (127 - s) : s;
    const float* gp = gates + (size_t)dir * 131072 + (size_t)b * 2048;
    float* cp = cbuf + (size_t)dir * 32768 + (size_t)b * 512;
    float* hp = hbuf + (size_t)t * 65536 + (size_t)b * 1024 + (size_t)dir * 512;
    for (int e = tid; e < 512; e += 256) {
        float ig = gp[e], fg = gp[512 + e], gg = gp[1024 + e], og = gp[1536 + e];
        float cprev = (s > 0) ? cp[e] : 0.0f;
        float c = sigm(fg) * cprev + sigm(ig) * tanhf(gg);
        cp[e] = c;
        hp[e] = sigm(og) * tanhf(c);
    }
}

// ---------------- mean pool + Wout ----------------
__global__ void out_k(const float* __restrict__ h1, const float* __restrict__ Wout,
                      float* __restrict__ out) {
    int b = blockIdx.x;
    int tid = threadIdx.x;
    __shared__ float pooled[1024];
    __shared__ float red[4][256];
#pragma unroll
    for (int k = 0; k < 4; k++) {
        int e = tid + k * 256;
        float s = 0.0f;
        for (int t = 0; t < 128; t++) s += h1[(size_t)t * 65536 + (size_t)b * 1024 + e];
        pooled[e] = s * (1.0f / 128.0f);
    }
    __syncthreads();
    float o4[4] = {0.f, 0.f, 0.f, 0.f};
#pragma unroll
    for (int k = 0; k < 4; k++) {
        int e = tid + k * 256;
        float pv = pooled[e];
        const float* wr = &Wout[(size_t)e * 4];
#pragma unroll
        for (int o = 0; o < 4; o++) o4[o] += pv * wr[o];
    }
#pragma unroll
    for (int o = 0; o < 4; o++) red[o][tid] = o4[o];
    __syncthreads();
    for (int st = 128; st > 0; st >>= 1) {
        if (tid < st)
#pragma unroll
            for (int o = 0; o < 4; o++) red[o][tid] += red[o][tid + st];
        __syncthreads();
    }
    if (tid < 4) out[b * 4 + tid] = red[tid][0];
}

// ---------------- launcher ----------------
extern "C" void kernel_launch(void* const* d_in, const int* in_sizes, int n_in,
                              void* d_out, int out_size) {
    const int*   src        = (const int*)d_in[0];
    const int*   wsrc       = (const int*)d_in[1];
    const float* char_table = (const float*)d_in[2];
    const float* word_table = (const float*)d_in[3];
    const float* w_bi  = (const float*)d_in[4];
    const float* b_bi  = (const float*)d_in[5];
    const float* w_tri = (const float*)d_in[6];
    const float* b_tri = (const float*)d_in[7];
    const float* Wa    = (const float*)d_in[8];
    const float* ba    = (const float*)d_in[9];
    const float* ua    = (const float*)d_in[10];
    const float* W1    = (const float*)d_in[11];
    const float* wih0  = (const float*)d_in[12];
    const float* whh0  = (const float*)d_in[13];
    const float* b0    = (const float*)d_in[14];
    const float* wih1  = (const float*)d_in[15];
    const float* whh1  = (const float*)d_in[16];
    const float* b1    = (const float*)d_in[17];
    const float* Wout  = (const float*)d_in[18];
    float* out = (float*)d_out;

    float *p_cat, *p_scorep, *p_we, *p_feats, *p_xg0, *p_xg1, *p_h0, *p_h1;
    float *p_c, *p_gates, *p_Wcat, *p_bcat, *p_WaT, *p_W1T, *p_pe;
    cudaGetSymbolAddress((void**)&p_cat, g_cat);
    cudaGetSymbolAddress((void**)&p_scorep, g_scorep);
    cudaGetSymbolAddress((void**)&p_we, g_we);
    cudaGetSymbolAddress((void**)&p_feats, g_feats);
    cudaGetSymbolAddress((void**)&p_xg0, g_xg0);
    cudaGetSymbolAddress((void**)&p_xg1, g_xg1);
    cudaGetSymbolAddress((void**)&p_h0, g_h0);
    cudaGetSymbolAddress((void**)&p_h1, g_h1);
    cudaGetSymbolAddress((void**)&p_c, g_cst);
    cudaGetSymbolAddress((void**)&p_gates, g_gates);
    cudaGetSymbolAddress((void**)&p_Wcat, g_Wcat);
    cudaGetSymbolAddress((void**)&p_bcat, g_bcat);
    cudaGetSymbolAddress((void**)&p_WaT, g_WaT);
    cudaGetSymbolAddress((void**)&p_W1T, g_W1T);
    cudaGetSymbolAddress((void**)&p_pe, g_pe);

    // weight prep
    prep_wcat_k<<<512, 256>>>(w_bi, b_bi, w_tri, b_tri);
    prep_misc_k<<<512, 256>>>(Wa, W1);

    // cat = gathered char embeddings @ Wcat^T  (+ bias + PE)
    gemm_k<1, 1><<<dim3(4, 1280, 1), 256>>>(
        nullptr, 0, p_Wcat, 768, 0, p_cat, 512, 0, p_bcat, 0, 768,
        src, char_table, p_pe, nullptr, nullptr);

    // attention scores: tanh(cat @ Wa + ba) . ua  -> partials
    gemm_k<0, 2><<<dim3(4, 1280, 1), 256>>>(
        p_cat, 512, p_WaT, 512, 0, nullptr, 0, 0, ba, 0, 512,
        nullptr, nullptr, nullptr, ua, p_scorep);

    // softmax + weighted sum
    attn_k<<<8192, 256>>>(p_cat, p_scorep, p_we);

    // feats[:, :256] = we @ W1  (permuted rows -> [t][b] layout)
    gemm_k<0, 3><<<dim3(2, 64, 1), 256>>>(
        p_we, 512, p_W1T, 512, 0, p_feats, 512, 0, nullptr, 0, 512,
        nullptr, nullptr, nullptr, nullptr, nullptr);

    // feats[:, 256:512] = word_table[word_src]
    wgather_k<<<8192, 64>>>(wsrc, word_table, p_feats);

    // layer-0 input gates (both dirs, z-batched)
    gemm_k<0, 0><<<dim3(16, 64, 2), 256>>>(
        p_feats, 512, wih0, 512, (long long)2048 * 512, p_xg0, 2048,
        (long long)8192 * 2048, b0, 2048, 512,
        nullptr, nullptr, nullptr, nullptr, nullptr);

    // layer-0 recurrence
    for (int s = 0; s < 128; s++) {
        lstm_gates_k<<<dim3(64, 1, 2), 256>>>(p_h0, whh0, p_xg0, p_gates, s);
        lstm_update_k<<<dim3(64, 1, 2), 256>>>(p_gates, p_c, p_h0, s);
    }

    // layer-1 input gates
    gemm_k<0, 0><<<dim3(16, 64, 2), 256>>>(
        p_h0, 1024, wih1, 1024, (long long)2048 * 1024, p_xg1, 2048,
        (long long)8192 * 2048, b1, 2048, 1024,
        nullptr, nullptr, nullptr, nullptr, nullptr);

    // layer-1 recurrence
    for (int s = 0; s < 128; s++) {
        lstm_gates_k<<<dim3(64, 1, 2), 256>>>(p_h1, whh1, p_xg1, p_gates, s);
        lstm_update_k<<<dim3(64, 1, 2), 256>>>(p_gates, p_c, p_h1, s);
    }

    // mean pool + output projection
    out_k<<<64, 256>>>(p_h1, Wout, out);
}

// round 9
// speedup vs baseline: 1.0051x; 1.0051x over previous
#include <cuda_runtime.h>
#include <math.h>

// ---- problem constants: B=64, W=128, C=20, D=256, H=512, G=2048 ----
// NW = 8192 words, NC = 163840 char positions.

// ---------------- device scratch (no allocations allowed) ----------------
__device__ float g_cat[163840 * 512];        // [NC][512]
__device__ float g_scorep[163840 * 4];       // [NC][4] partial score sums
__device__ float g_we[8192 * 512];           // [NW][512]
__device__ float g_feats[8192 * 512];        // [t][b][512]
__device__ float g_xg0[2 * 8192 * 2048];     // [dir][t*64+b][2048]
__device__ float g_xg1[2 * 8192 * 2048];
__device__ float g_h0[128 * 64 * 1024];      // [t][b][dir*512+e]
__device__ float g_h1[128 * 64 * 1024];
__device__ float g_cst[2 * 64 * 512];        // cell state per dir
__device__ float g_gates[2 * 64 * 2048];     // per-step gate buffer
__device__ float g_Wcat[512 * 768];          // packed conv weights (NT)
__device__ float g_bcat[512];
__device__ float g_WaT[512 * 512];           // Wa transposed (NT)
__device__ float g_W1T[256 * 512];           // W1 transposed (NT)
__device__ float g_pe[20 * 256];             // positional encoding

__device__ __forceinline__ float sigm(float x) { return 1.0f / (1.0f + expf(-x)); }

// ---------------- prep kernels ----------------
__global__ void prep_wcat_k(const float* __restrict__ wbi, const float* __restrict__ bbi,
                            const float* __restrict__ wtri, const float* __restrict__ btri) {
    int o = blockIdx.x;  // 0..511
    for (int k = threadIdx.x; k < 768; k += 256) {
        int grp = k >> 8, i = k & 255;
        float v;
        if (o < 256) v = (grp < 2) ? wbi[(o * 256 + i) * 2 + grp] : 0.0f;
        else         v = wtri[((o - 256) * 256 + i) * 3 + grp];
        g_Wcat[o * 768 + k] = v;
    }
    if (threadIdx.x == 0) g_bcat[o] = (o < 256) ? bbi[o] : btri[o - 256];
}

__global__ void prep_misc_k(const float* __restrict__ Wa, const float* __restrict__ W1) {
    int e = blockIdx.x;  // 0..511
    for (int d = threadIdx.x; d < 512; d += 256)
        g_WaT[e * 512 + d] = Wa[d * 512 + e];
    if (e < 256)
        for (int d = threadIdx.x; d < 512; d += 256)
            g_W1T[e * 512 + d] = W1[d * 256 + e];
    if (e < 20) {
        int o = threadIdx.x;  // 0..255
        int p = o >> 1;
        float ang = (float)e * expf(-(float)(2 * p) * (logf(10000.0f) / 256.0f));
        g_pe[e * 256 + o] = (o & 1) ? cosf(ang) : sinf(ang);
    }
}

// ---------------- generic NT SGEMM, 128x128 tile, 256 threads, 8x8 micro ----
// C[M,N] = A[M,K] @ B[N,K]^T  (+ epilogue)
// AMODE 0: row-major A (lda).  AMODE 1: char-table gather (K=768).
// EMODE 0: C = acc + bias[z*sBias + col]          (z-batched via gridDim.z)
// EMODE 1: C = acc + bias[col] + pe[row%20][col&255]
// EMODE 2: scorep[row*4 + bx] = sum_col tanh(acc+bias[col])*ua[col]  (no C)
// EMODE 3: permuted rows: orow = (row&127)*64 + (row>>7)             (no bias)
template <int AMODE, int EMODE>
__global__ void __launch_bounds__(256) gemm_k(
    const float* __restrict__ A, int lda,
    const float* __restrict__ Bm, int ldb, long long sB,
    float* __restrict__ Cm, int ldc, long long sC,
    const float* __restrict__ bias, int sBias,
    int K,
    const int* __restrict__ srcI, const float* __restrict__ tbl,
    const float* __restrict__ peA, const float* __restrict__ uaV,
    float* __restrict__ scorepO) {
    __shared__ float As[16 * 132];
    __shared__ float Bs[16 * 132];

    const int z = blockIdx.z;
    const int row0 = blockIdx.y * 128;
    const int col0 = blockIdx.x * 128;
    const int tid = threadIdx.x;
    const int ty = tid >> 4, tx = tid & 15;

    const int mL = tid >> 1;          // 0..127, shared by A & B loads
    const int q0 = (tid & 1) * 2;     // k-quad base (q0, q0+1)
    const int rowL = row0 + mL;
    int tw = 0;
    if (AMODE == 1) tw = rowL % 20;
    const float* Arow = (AMODE == 0) ? (A + (size_t)rowL * lda) : (const float*)0;
    const float* Brow = Bm + (size_t)z * sB + (size_t)(col0 + mL) * ldb;

    float acc[8][8];
#pragma unroll
    for (int i = 0; i < 8; i++)
#pragma unroll
        for (int j = 0; j < 8; j++) acc[i][j] = 0.0f;

    for (int kt = 0; kt < K; kt += 16) {
        float4 av[2], bv[2];
#pragma unroll
        for (int r = 0; r < 2; r++) {
            int q = q0 + r;
            int k = kt + q * 4;
            if (AMODE == 0) {
                av[r] = *(const float4*)(Arow + k);
            } else {
                int grp = k >> 8, ii = k & 255;
                if (tw + grp < 20) {
                    int ci = srcI[rowL + grp];
                    av[r] = *(const float4*)(tbl + (size_t)ci * 256 + ii);
                } else {
                    av[r] = make_float4(0.f, 0.f, 0.f, 0.f);
                }
            }
            bv[r] = *(const float4*)(Brow + k);
        }
        __syncthreads();
#pragma unroll
        for (int r = 0; r < 2; r++) {
            int q = q0 + r;
            As[(q * 4 + 0) * 132 + mL] = av[r].x;
            As[(q * 4 + 1) * 132 + mL] = av[r].y;
            As[(q * 4 + 2) * 132 + mL] = av[r].z;
            As[(q * 4 + 3) * 132 + mL] = av[r].w;
            Bs[(q * 4 + 0) * 132 + mL] = bv[r].x;
            Bs[(q * 4 + 1) * 132 + mL] = bv[r].y;
            Bs[(q * 4 + 2) * 132 + mL] = bv[r].z;
            Bs[(q * 4 + 3) * 132 + mL] = bv[r].w;
        }
        __syncthreads();
#pragma unroll
        for (int k = 0; k < 16; k++) {
            float4 a0 = *(const float4*)&As[k * 132 + ty * 8];
            float4 a1 = *(const float4*)&As[k * 132 + ty * 8 + 4];
            float4 b0 = *(const float4*)&Bs[k * 132 + tx * 8];
            float4 b1 = *(const float4*)&Bs[k * 132 + tx * 8 + 4];
            float aa[8] = {a0.x, a0.y, a0.z, a0.w, a1.x, a1.y, a1.z, a1.w};
            float bb[8] = {b0.x, b0.y, b0.z, b0.w, b1.x, b1.y, b1.z, b1.w};
#pragma unroll
            for (int i = 0; i < 8; i++)
#pragma unroll
                for (int j = 0; j < 8; j++) acc[i][j] += aa[i] * bb[j];
        }
    }

    if constexpr (EMODE == 2) {
#pragma unroll
        for (int i = 0; i < 8; i++) {
            int row = row0 + ty * 8 + i;
            float s = 0.0f;
#pragma unroll
            for (int j = 0; j < 8; j++) {
                int col = col0 + tx * 8 + j;
                s += tanhf(acc[i][j] + bias[col]) * uaV[col];
            }
            s += __shfl_xor_sync(0xffffffffu, s, 8);
            s += __shfl_xor_sync(0xffffffffu, s, 4);
            s += __shfl_xor_sync(0xffffffffu, s, 2);
            s += __shfl_xor_sync(0xffffffffu, s, 1);
            if (tx == 0) scorepO[(size_t)row * 4 + blockIdx.x] = s;
        }
    } else {
        float* Cz = Cm + (size_t)z * sC;
#pragma unroll
        for (int i = 0; i < 8; i++) {
            int row = row0 + ty * 8 + i;
            float* crow;
            if constexpr (EMODE == 3) {
                int orow = (row & 127) * 64 + (row >> 7);
                crow = Cz + (size_t)orow * ldc;
            } else {
                crow = Cz + (size_t)row * ldc;
            }
            int trow = 0;
            if constexpr (EMODE == 1) trow = row % 20;
#pragma unroll
            for (int j = 0; j < 8; j++) {
                int col = col0 + tx * 8 + j;
                float v = acc[i][j];
                if constexpr (EMODE == 0) v += bias[(size_t)z * sBias + col];
                if constexpr (EMODE == 1) v += bias[col] + peA[trow * 256 + (col & 255)];
                crow[col] = v;
            }
        }
    }
}

// ---------------- attention: softmax over 20 chars + weighted sum ----------------
__global__ void attn_k(const float* __restrict__ cat, const float* __restrict__ scorep,
                       float* __restrict__ we) {
    int n = blockIdx.x;  // word index, 0..8191
    int tid = threadIdx.x;
    __shared__ float a[20];
    if (tid < 20) {
        const float* sp = scorep + (size_t)(n * 20 + tid) * 4;
        a[tid] = sp[0] + sp[1] + sp[2] + sp[3];
    }
    __syncthreads();
    if (tid == 0) {
        float mx = a[0];
        for (int t = 1; t < 20; t++) mx = fmaxf(mx, a[t]);
        float s = 0.0f;
        for (int t = 0; t < 20; t++) { a[t] = expf(a[t] - mx); s += a[t]; }
        float inv = 1.0f / s;
        for (int t = 0; t < 20; t++) a[t] *= inv;
    }
    __syncthreads();
    const float* cp = cat + (size_t)n * 20 * 512;
    for (int e = tid; e < 512; e += 256) {
        float acc = 0.0f;
#pragma unroll
        for (int t = 0; t < 20; t++) acc += a[t] * cp[t * 512 + e];
        we[(size_t)n * 512 + e] = acc;
    }
}

// ---------------- word table gather into feats[..][256:512] ----------------
__global__ void wgather_k(const int* __restrict__ wsrc, const float* __restrict__ wtab,
                          float* __restrict__ feats) {
    int n = blockIdx.x;  // 0..8191, n = b*128 + w
    int b = n >> 7, w = n & 127;
    int orow = w * 64 + b;
    const float4* sp = (const float4*)(wtab + (size_t)wsrc[n] * 256);
    float4* dp = (float4*)(feats + (size_t)orow * 512 + 256);
    dp[threadIdx.x] = sp[threadIdx.x];  // 64 threads x float4 = 256 floats
}

// ---------------- LSTM recurrent gates GEMM: g = xg + h_prev @ whh^T -------
// grid (64, 1, 2): 64 gate-chunks of 32, z = dir.  tile M=64 x N=32, K=512.
__global__ void __launch_bounds__(256) lstm_gates_k(
    const float* __restrict__ h, const float* __restrict__ whh,
    const float* __restrict__ xg, float* __restrict__ gates, int s) {
    __shared__ float As[16 * 68];
    __shared__ float Bs[16 * 36];
    int dir = blockIdx.z;
    int col0 = blockIdx.x * 32;
    int tid = threadIdx.x;
    int t = dir ? (127 - s) : s;
    int tprev = dir ? (128 - s) : (s - 1);
    const float* Abase = h + (size_t)tprev * 65536 + (size_t)dir * 512;
    const float* Bbase = whh + (size_t)dir * 2048 * 512 + (size_t)col0 * 512;
    int mA = tid >> 2, qA = tid & 3;
    int ty = tid >> 4, tx = tid & 15;

    float acc[4][2] = {{0.f, 0.f}, {0.f, 0.f}, {0.f, 0.f}, {0.f, 0.f}};

    if (s > 0) {
        for (int kt = 0; kt < 512; kt += 16) {
            float4 a = *(const float4*)(Abase + (size_t)mA * 1024 + kt + qA * 4);
            float4 b = make_float4(0.f, 0.f, 0.f, 0.f);
            if (tid < 128)
                b = *(const float4*)(Bbase + (size_t)(tid >> 2) * 512 + kt + (tid & 3) * 4);
            __syncthreads();
            As[(qA * 4 + 0) * 68 + mA] = a.x;
            As[(qA * 4 + 1) * 68 + mA] = a.y;
            As[(qA * 4 + 2) * 68 + mA] = a.z;
            As[(qA * 4 + 3) * 68 + mA] = a.w;
            if (tid < 128) {
                int nB = tid >> 2, qB = tid & 3;
                Bs[(qB * 4 + 0) * 36 + nB] = b.x;
                Bs[(qB * 4 + 1) * 36 + nB] = b.y;
                Bs[(qB * 4 + 2) * 36 + nB] = b.z;
                Bs[(qB * 4 + 3) * 36 + nB] = b.w;
            }
            __syncthreads();
#pragma unroll
            for (int k = 0; k < 16; k++) {
                float4 a4 = *(const float4*)&As[k * 68 + ty * 4];
                float2 b2 = *(const float2*)&Bs[k * 36 + tx * 2];
                acc[0][0] += a4.x * b2.x; acc[0][1] += a4.x * b2.y;
                acc[1][0] += a4.y * b2.x; acc[1][1] += a4.y * b2.y;
                acc[2][0] += a4.z * b2.x; acc[2][1] += a4.z * b2.y;
                acc[3][0] += a4.w * b2.x; acc[3][1] += a4.w * b2.y;
            }
        }
    }
    const float* xgp = xg + ((size_t)dir * 8192 + (size_t)t * 64) * 2048;
    float* gp = gates + (size_t)dir * 131072;
#pragma unroll
    for (int i = 0; i < 4; i++) {
        int brow = ty * 4 + i;
#pragma unroll
        for (int j = 0; j < 2; j++) {
            int g = col0 + tx * 2 + j;
            gp[(size_t)brow * 2048 + g] = acc[i][j] + xgp[(size_t)brow * 2048 + g];
        }
    }
}

// ---------------- LSTM pointwise update ----------------
__global__ void lstm_update_k(const float* __restrict__ gates, float* __restrict__ cbuf,
                              float* __restrict__ hbuf, int s) {
    int dir = blockIdx.z;
    int b = blockIdx.x;
    int tid = threadIdx.x;
    int t = dir ? (127 - s) : s;
    const float* gp = gates + (size_t)dir * 131072 + (size_t)b * 2048;
    float* cp = cbuf + (size_t)dir * 32768 + (size_t)b * 512;
    float* hp = hbuf + (size_t)t * 65536 + (size_t)b * 1024 + (size_t)dir * 512;
    for (int e = tid; e < 512; e += 256) {
        float ig = gp[e], fg = gp[512 + e], gg = gp[1024 + e], og = gp[1536 + e];
        float cprev = (s > 0) ? cp[e] : 0.0f;
        float c = sigm(fg) * cprev + sigm(ig) * tanhf(gg);
        cp[e] = c;
        hp[e] = sigm(og) * tanhf(c);
    }
}

// ---------------- mean pool + Wout ----------------
__global__ void out_k(const float* __restrict__ h1, const float* __restrict__ Wout,
                      float* __restrict__ out) {
    int b = blockIdx.x;
    int tid = threadIdx.x;
    __shared__ float pooled[1024];
    __shared__ float red[4][256];
#pragma unroll
    for (int k = 0; k < 4; k++) {
        int e = tid + k * 256;
        float s = 0.0f;
        for (int t = 0; t < 128; t++) s += h1[(size_t)t * 65536 + (size_t)b * 1024 + e];
        pooled[e] = s * (1.0f / 128.0f);
    }
    __syncthreads();
    float o4[4] = {0.f, 0.f, 0.f, 0.f};
#pragma unroll
    for (int k = 0; k < 4; k++) {
        int e = tid + k * 256;
        float pv = pooled[e];
        const float* wr = &Wout[(size_t)e * 4];
#pragma unroll
        for (int o = 0; o < 4; o++) o4[o] += pv * wr[o];
    }
#pragma unroll
    for (int o = 0; o < 4; o++) red[o][tid] = o4[o];
    __syncthreads();
    for (int st = 128; st > 0; st >>= 1) {
        if (tid < st)
#pragma unroll
            for (int o = 0; o < 4; o++) red[o][tid] += red[o][tid + st];
        __syncthreads();
    }
    if (tid < 4) out[b * 4 + tid] = red[tid][0];
}

// ---------------- launcher ----------------
extern "C" void kernel_launch(void* const* d_in, const int* in_sizes, int n_in,
                              void* d_out, int out_size) {
    const int*   src        = (const int*)d_in[0];
    const int*   wsrc       = (const int*)d_in[1];
    const float* char_table = (const float*)d_in[2];
    const float* word_table = (const float*)d_in[3];
    const float* w_bi  = (const float*)d_in[4];
    const float* b_bi  = (const float*)d_in[5];
    const float* w_tri = (const float*)d_in[6];
    const float* b_tri = (const float*)d_in[7];
    const float* Wa    = (const float*)d_in[8];
    const float* ba    = (const float*)d_in[9];
    const float* ua    = (const float*)d_in[10];
    const float* W1    = (const float*)d_in[11];
    const float* wih0  = (const float*)d_in[12];
    const float* whh0  = (const float*)d_in[13];
    const float* b0    = (const float*)d_in[14];
    const float* wih1  = (const float*)d_in[15];
    const float* whh1  = (const float*)d_in[16];
    const float* b1    = (const float*)d_in[17];
    const float* Wout  = (const float*)d_in[18];
    float* out = (float*)d_out;

    float *p_cat, *p_scorep, *p_we, *p_feats, *p_xg0, *p_xg1, *p_h0, *p_h1;
    float *p_c, *p_gates, *p_Wcat, *p_bcat, *p_WaT, *p_W1T, *p_pe;
    cudaGetSymbolAddress((void**)&p_cat, g_cat);
    cudaGetSymbolAddress((void**)&p_scorep, g_scorep);
    cudaGetSymbolAddress((void**)&p_we, g_we);
    cudaGetSymbolAddress((void**)&p_feats, g_feats);
    cudaGetSymbolAddress((void**)&p_xg0, g_xg0);
    cudaGetSymbolAddress((void**)&p_xg1, g_xg1);
    cudaGetSymbolAddress((void**)&p_h0, g_h0);
    cudaGetSymbolAddress((void**)&p_h1, g_h1);
    cudaGetSymbolAddress((void**)&p_c, g_cst);
    cudaGetSymbolAddress((void**)&p_gates, g_gates);
    cudaGetSymbolAddress((void**)&p_Wcat, g_Wcat);
    cudaGetSymbolAddress((void**)&p_bcat, g_bcat);
    cudaGetSymbolAddress((void**)&p_WaT, g_WaT);
    cudaGetSymbolAddress((void**)&p_W1T, g_W1T);
    cudaGetSymbolAddress((void**)&p_pe, g_pe);

    // weight prep
    prep_wcat_k<<<512, 256>>>(w_bi, b_bi, w_tri, b_tri);
    prep_misc_k<<<512, 256>>>(Wa, W1);

    // cat = gathered char embeddings @ Wcat^T  (+ bias + PE)
    gemm_k<1, 1><<<dim3(4, 1280, 1), 256>>>(
        nullptr, 0, p_Wcat, 768, 0, p_cat, 512, 0, p_bcat, 0, 768,
        src, char_table, p_pe, nullptr, nullptr);

    // attention scores: tanh(cat @ Wa + ba) . ua  -> partials
    gemm_k<0, 2><<<dim3(4, 1280, 1), 256>>>(
        p_cat, 512, p_WaT, 512, 0, nullptr, 0, 0, ba, 0, 512,
        nullptr, nullptr, nullptr, ua, p_scorep);

    // softmax + weighted sum
    attn_k<<<8192, 256>>>(p_cat, p_scorep, p_we);

    // feats[:, :256] = we @ W1  (permuted rows -> [t][b] layout)
    gemm_k<0, 3><<<dim3(2, 64, 1), 256>>>(
        p_we, 512, p_W1T, 512, 0, p_feats, 512, 0, nullptr, 0, 512,
        nullptr, nullptr, nullptr, nullptr, nullptr);

    // feats[:, 256:512] = word_table[word_src]
    wgather_k<<<8192, 64>>>(wsrc, word_table, p_feats);

    // layer-0 input gates (both dirs, z-batched)
    gemm_k<0, 0><<<dim3(16, 64, 2), 256>>>(
        p_feats, 512, wih0, 512, (long long)2048 * 512, p_xg0, 2048,
        (long long)8192 * 2048, b0, 2048, 512,
        nullptr, nullptr, nullptr, nullptr, nullptr);

    // layer-0 recurrence
    for (int s = 0; s < 128; s++) {
        lstm_gates_k<<<dim3(64, 1, 2), 256>>>(p_h0, whh0, p_xg0, p_gates, s);
        lstm_update_k<<<dim3(64, 1, 2), 256>>>(p_gates, p_c, p_h0, s);
    }

    // layer-1 input gates
    gemm_k<0, 0><<<dim3(16, 64, 2), 256>>>(
        p_h0, 1024, wih1, 1024, (long long)2048 * 1024, p_xg1, 2048,
        (long long)8192 * 2048, b1, 2048, 1024,
        nullptr, nullptr, nullptr, nullptr, nullptr);

    // layer-1 recurrence
    for (int s = 0; s < 128; s++) {
        lstm_gates_k<<<dim3(64, 1, 2), 256>>>(p_h1, whh1, p_xg1, p_gates, s);
        lstm_update_k<<<dim3(64, 1, 2), 256>>>(p_gates, p_c, p_h1, s);
    }

    // mean pool + output projection
    out_k<<<64, 256>>>(p_h1, Wout, out);
}

// round 17
// speedup vs baseline: 1.4808x; 1.4733x over previous
#include <cuda_runtime.h>
#include <math.h>

// ---- constants: B=64, W=128, C=20, D=256, H=512, G=2048; NW=8192 ----

// ---------------- device scratch ----------------
__device__ float g_T[3 * 128 * 512];     // char->cat tables
__device__ float g_TA[3 * 128 * 512];    // char->(cat@Wa) tables
__device__ float g_PB[20 * 512];         // (bcat+pe[t])@Wa + ba
__device__ float g_we[8192 * 512];
__device__ float g_feats[8192 * 512];    // [t][b][512]
__device__ float g_xg0[2L * 8192 * 2048];
__device__ float g_xg1[2L * 8192 * 2048];
__device__ float g_h0[128 * 64 * 1024];
__device__ float g_h1[128 * 64 * 1024];
__device__ float g_cst[2 * 64 * 512];
__device__ float g_gates[2 * 64 * 2048];
__device__ float g_Wcat[512 * 768];
__device__ float g_bcat[512];
__device__ float g_W1T[256 * 512];
__device__ float g_pe[20 * 256];

__device__ __forceinline__ float sigm(float x) { return 1.0f / (1.0f + expf(-x)); }

// ================= prep =================
__global__ void prep_wcat_k(const float* __restrict__ wbi, const float* __restrict__ bbi,
                            const float* __restrict__ wtri, const float* __restrict__ btri) {
    int o = blockIdx.x;
    for (int k = threadIdx.x; k < 768; k += 256) {
        int grp = k >> 8, i = k & 255;
        float v;
        if (o < 256) v = (grp < 2) ? wbi[(o * 256 + i) * 2 + grp] : 0.0f;
        else         v = wtri[((o - 256) * 256 + i) * 3 + grp];
        g_Wcat[o * 768 + k] = v;
    }
    if (threadIdx.x == 0) g_bcat[o] = (o < 256) ? bbi[o] : btri[o - 256];
}
__global__ void prep_misc_k(const float* __restrict__ W1) {
    int e = blockIdx.x;  // 0..255
    for (int d = threadIdx.x; d < 512; d += 256)
        g_W1T[e * 512 + d] = W1[d * 256 + e];
    if (e < 20) {
        int o = threadIdx.x;
        int p = o >> 1;
        float ang = (float)e * expf(-(float)(2 * p) * (logf(10000.0f) / 256.0f));
        g_pe[e * 256 + o] = (o & 1) ? cosf(ang) : sinf(ang);
    }
}
// T[g][c][o] = sum_i Wcat[o][g*256+i] * emb[c][i]
__global__ void tbl_k(const float* __restrict__ emb) {
    int gc = blockIdx.x;  // 0..383
    int g = gc >> 7, c = gc & 127;
    __shared__ float er[256];
    er[threadIdx.x] = emb[c * 256 + threadIdx.x];
    __syncthreads();
    for (int o = threadIdx.x; o < 512; o += 256) {
        const float* w = g_Wcat + (size_t)o * 768 + g * 256;
        float s = 0.0f;
#pragma unroll 8
        for (int i = 0; i < 256; i++) s += w[i] * er[i];
        g_T[(size_t)gc * 512 + o] = s;
    }
}
// TA[gc][e] = sum_d T[gc][d] * Wa[d][e]
__global__ void ta_k(const float* __restrict__ Wa) {
    int gc = blockIdx.x;
    __shared__ float tr[512];
    tr[threadIdx.x] = g_T[(size_t)gc * 512 + threadIdx.x];
    tr[threadIdx.x + 256] = g_T[(size_t)gc * 512 + threadIdx.x + 256];
    __syncthreads();
    for (int e = threadIdx.x; e < 512; e += 256) {
        float s = 0.0f;
#pragma unroll 8
        for (int d = 0; d < 512; d++) s += tr[d] * Wa[(size_t)d * 512 + e];
        g_TA[(size_t)gc * 512 + e] = s;
    }
}
// PB[t][e] = ba[e] + sum_d (bcat[d]+pe[t][d&255]) * Wa[d][e]
__global__ void pb_k(const float* __restrict__ Wa, const float* __restrict__ ba) {
    int t = blockIdx.x;
    int e = threadIdx.x;  // 512 threads
    __shared__ float vr[512];
    vr[e] = g_bcat[e] + g_pe[t * 256 + (e & 255)];
    __syncthreads();
    float s = ba[e];
#pragma unroll 8
    for (int d = 0; d < 512; d++) s += vr[d] * Wa[(size_t)d * 512 + e];
    g_PB[t * 512 + e] = s;
}

// ================= fused score + softmax + weighted-sum (NEW, under test) ===
__global__ void __launch_bounds__(256) scoreattn_k(const int* __restrict__ src,
                                                   const float* __restrict__ ua,
                                                   float* __restrict__ we) {
    int n = blockIdx.x;
    int tid = threadIdx.x, lane = tid & 31, w = tid >> 5;
    __shared__ int ci[20];
    __shared__ float sc[20];
    if (tid < 20) ci[tid] = src[n * 20 + tid];
    __syncthreads();
    for (int t = w; t < 20; t += 8) {
        const float* p0 = g_TA + (size_t)ci[t] * 512;
        const float* p1 = (t < 19) ? g_TA + (size_t)(128 + ci[t + 1]) * 512 : nullptr;
        const float* p2 = (t < 18) ? g_TA + (size_t)(256 + ci[t + 2]) * 512 : nullptr;
        const float* pb = g_PB + t * 512;
        float s = 0.0f;
        for (int e = lane; e < 512; e += 32) {
            float v = p0[e] + pb[e];
            if (p1) v += p1[e];
            if (p2) v += p2[e];
            s += tanhf(v) * ua[e];
        }
#pragma unroll
        for (int o = 16; o; o >>= 1) s += __shfl_xor_sync(0xffffffffu, s, o);
        if (lane == 0) sc[t] = s;
    }
    __syncthreads();
    if (tid == 0) {
        float mx = sc[0];
        for (int t = 1; t < 20; t++) mx = fmaxf(mx, sc[t]);
        float ss = 0.0f;
        for (int t = 0; t < 20; t++) { sc[t] = expf(sc[t] - mx); ss += sc[t]; }
        float inv = 1.0f / ss;
        for (int t = 0; t < 20; t++) sc[t] *= inv;
    }
    __syncthreads();
    for (int r = 0; r < 2; r++) {
        int e = tid + r * 256;
        float acc = 0.0f;
#pragma unroll
        for (int t = 0; t < 20; t++) {
            float v = g_T[(size_t)ci[t] * 512 + e] + g_bcat[e] + g_pe[t * 256 + (e & 255)];
            if (t < 19) v += g_T[(size_t)(128 + ci[t + 1]) * 512 + e];
            if (t < 18) v += g_T[(size_t)(256 + ci[t + 2]) * 512 + e];
            acc += sc[t] * v;
        }
        we[(size_t)n * 512 + e] = acc;
    }
}

// ================= KNOWN-GOOD (round-7) FFMA NT SGEMM =================
// C[M,N] = A[M,K] @ B[N,K]^T  (+ epilogue)
// EMODE 0: C = acc + bias[z*sBias + col]   (z-batched)
// EMODE 3: permuted rows: orow = (row&127)*64 + (row>>7), no bias
template <int AMODE, int EMODE>
__global__ void __launch_bounds__(256) gemm_k(
    const float* __restrict__ A, int lda,
    const float* __restrict__ Bm, int ldb, long long sB,
    float* __restrict__ Cm, int ldc, long long sC,
    const float* __restrict__ bias, int sBias,
    int K,
    const int* __restrict__ srcI, const float* __restrict__ tbl,
    const float* __restrict__ peA, const float* __restrict__ uaV,
    float* __restrict__ scorepO) {
    __shared__ float As[16 * 132];
    __shared__ float Bs[16 * 132];

    const int z = blockIdx.z;
    const int row0 = blockIdx.y * 128;
    const int col0 = blockIdx.x * 128;
    const int tid = threadIdx.x;
    const int ty = tid >> 4, tx = tid & 15;

    const int mL = tid >> 1;
    const int q0 = (tid & 1) * 2;
    const int rowL = row0 + mL;
    const float* Arow = A + (size_t)rowL * lda;
    const float* Brow = Bm + (size_t)z * sB + (size_t)(col0 + mL) * ldb;

    float acc[8][8];
#pragma unroll
    for (int i = 0; i < 8; i++)
#pragma unroll
        for (int j = 0; j < 8; j++) acc[i][j] = 0.0f;

    for (int kt = 0; kt < K; kt += 16) {
        float4 av[2], bv[2];
#pragma unroll
        for (int r = 0; r < 2; r++) {
            int k = kt + (q0 + r) * 4;
            av[r] = *(const float4*)(Arow + k);
            bv[r] = *(const float4*)(Brow + k);
        }
        __syncthreads();
#pragma unroll
        for (int r = 0; r < 2; r++) {
            int q = q0 + r;
            As[(q * 4 + 0) * 132 + mL] = av[r].x;
            As[(q * 4 + 1) * 132 + mL] = av[r].y;
            As[(q * 4 + 2) * 132 + mL] = av[r].z;
            As[(q * 4 + 3) * 132 + mL] = av[r].w;
            Bs[(q * 4 + 0) * 132 + mL] = bv[r].x;
            Bs[(q * 4 + 1) * 132 + mL] = bv[r].y;
            Bs[(q * 4 + 2) * 132 + mL] = bv[r].z;
            Bs[(q * 4 + 3) * 132 + mL] = bv[r].w;
        }
        __syncthreads();
#pragma unroll
        for (int k = 0; k < 16; k++) {
            float4 a0 = *(const float4*)&As[k * 132 + ty * 8];
            float4 a1 = *(const float4*)&As[k * 132 + ty * 8 + 4];
            float4 b0 = *(const float4*)&Bs[k * 132 + tx * 8];
            float4 b1 = *(const float4*)&Bs[k * 132 + tx * 8 + 4];
            float aa[8] = {a0.x, a0.y, a0.z, a0.w, a1.x, a1.y, a1.z, a1.w};
            float bb[8] = {b0.x, b0.y, b0.z, b0.w, b1.x, b1.y, b1.z, b1.w};
#pragma unroll
            for (int i = 0; i < 8; i++)
#pragma unroll
                for (int j = 0; j < 8; j++) acc[i][j] += aa[i] * bb[j];
        }
    }

    float* Cz = Cm + (size_t)z * sC;
#pragma unroll
    for (int i = 0; i < 8; i++) {
        int row = row0 + ty * 8 + i;
        float* crow;
        if constexpr (EMODE == 3) {
            int orow = (row & 127) * 64 + (row >> 7);
            crow = Cz + (size_t)orow * ldc;
        } else {
            crow = Cz + (size_t)row * ldc;
        }
#pragma unroll
        for (int j = 0; j < 8; j++) {
            int col = col0 + tx * 8 + j;
            float v = acc[i][j];
            if constexpr (EMODE == 0) v += bias[(size_t)z * sBias + col];
            crow[col] = v;
        }
    }
}

// ---------------- word table gather into feats[..][256:512] (fp32) ---------
__global__ void wgather_k(const int* __restrict__ wsrc, const float* __restrict__ wtab,
                          float* __restrict__ feats) {
    int n = blockIdx.x;
    int b = n >> 7, w = n & 127;
    int orow = w * 64 + b;
    const float4* sp = (const float4*)(wtab + (size_t)wsrc[n] * 256);
    float4* dp = (float4*)(feats + (size_t)orow * 512 + 256);
    dp[threadIdx.x] = sp[threadIdx.x];  // 64 threads x float4 = 256 floats
}

// ---------------- KNOWN-GOOD (round-7) LSTM recurrent gates GEMM -----------
__global__ void __launch_bounds__(256) lstm_gates_k(
    const float* __restrict__ h, const float* __restrict__ whh,
    const float* __restrict__ xg, float* __restrict__ gates, int s) {
    __shared__ float As[16 * 68];
    __shared__ float Bs[16 * 36];
    int dir = blockIdx.z;
    int col0 = blockIdx.x * 32;
    int tid = threadIdx.x;
    int t = dir ? (127 - s) : s;
    int tprev = dir ? (128 - s) : (s - 1);
    const float* Abase = h + (size_t)tprev * 65536 + (size_t)dir * 512;
    const float* Bbase = whh + (size_t)dir * 2048 * 512 + (size_t)col0 * 512;
    int mA = tid >> 2, qA = tid & 3;
    int ty = tid >> 4, tx = tid & 15;

    float acc[4][2] = {{0.f, 0.f}, {0.f, 0.f}, {0.f, 0.f}, {0.f, 0.f}};

    if (s > 0) {
        for (int kt = 0; kt < 512; kt += 16) {
            float4 a = *(const float4*)(Abase + (size_t)mA * 1024 + kt + qA * 4);
            float4 b = make_float4(0.f, 0.f, 0.f, 0.f);
            if (tid < 128)
                b = *(const float4*)(Bbase + (size_t)(tid >> 2) * 512 + kt + (tid & 3) * 4);
            __syncthreads();
            As[(qA * 4 + 0) * 68 + mA] = a.x;
            As[(qA * 4 + 1) * 68 + mA] = a.y;
            As[(qA * 4 + 2) * 68 + mA] = a.z;
            As[(qA * 4 + 3) * 68 + mA] = a.w;
            if (tid < 128) {
                int nB = tid >> 2, qB = tid & 3;
                Bs[(qB * 4 + 0) * 36 + nB] = b.x;
                Bs[(qB * 4 + 1) * 36 + nB] = b.y;
                Bs[(qB * 4 + 2) * 36 + nB] = b.z;
                Bs[(qB * 4 + 3) * 36 + nB] = b.w;
            }
            __syncthreads();
#pragma unroll
            for (int k = 0; k < 16; k++) {
                float4 a4 = *(const float4*)&As[k * 68 + ty * 4];
                float2 b2 = *(const float2*)&Bs[k * 36 + tx * 2];
                acc[0][0] += a4.x * b2.x; acc[0][1] += a4.x * b2.y;
                acc[1][0] += a4.y * b2.x; acc[1][1] += a4.y * b2.y;
                acc[2][0] += a4.z * b2.x; acc[2][1] += a4.z * b2.y;
                acc[3][0] += a4.w * b2.x; acc[3][1] += a4.w * b2.y;
            }
        }
    }
    const float* xgp = xg + ((size_t)dir * 8192 + (size_t)t * 64) * 2048;
    float* gp = gates + (size_t)dir * 131072;
#pragma unroll
    for (int i = 0; i < 4; i++) {
        int brow = ty * 4 + i;
#pragma unroll
        for (int j = 0; j < 2; j++) {
            int g = col0 + tx * 2 + j;
            gp[(size_t)brow * 2048 + g] = acc[i][j] + xgp[(size_t)brow * 2048 + g];
        }
    }
}

// ---------------- KNOWN-GOOD (round-7) LSTM pointwise update ----------------
__global__ void lstm_update_k(const float* __restrict__ gates, float* __restrict__ cbuf,
                              float* __restrict__ hbuf, int s) {
    int dir = blockIdx.z;
    int b = blockIdx.x;
    int tid = threadIdx.x;
    int t = dir ? (127 - s) : s;
    const float* gp = gates + (size_t)dir * 131072 + (size_t)b * 2048;
    float* cp = cbuf + (size_t)dir * 32768 + (size_t)b * 512;
    float* hp = hbuf + (size_t)t * 65536 + (size_t)b * 1024 + (size_t)dir * 512;
    for (int e = tid; e < 512; e += 256) {
        float ig = gp[e], fg = gp[512 + e], gg = gp[1024 + e], og = gp[1536 + e];
        float cprev = (s > 0) ? cp[e] : 0.0f;
        float c = sigm(fg) * cprev + sigm(ig) * tanhf(gg);
        cp[e] = c;
        hp[e] = sigm(og) * tanhf(c);
    }
}

// ---------------- mean pool + Wout ----------------
__global__ void out_k(const float* __restrict__ h1, const float* __restrict__ Wout,
                      float* __restrict__ out) {
    int b = blockIdx.x;
    int tid = threadIdx.x;
    __shared__ float red[4][256];
    float o4[4] = {0.f, 0.f, 0.f, 0.f};
#pragma unroll
    for (int k = 0; k < 4; k++) {
        int e = tid + k * 256;
        float s = 0.0f;
        for (int t = 0; t < 128; t++) s += h1[(size_t)t * 65536 + (size_t)b * 1024 + e];
        s *= (1.0f / 128.0f);
        const float* wr = &Wout[(size_t)e * 4];
#pragma unroll
        for (int o = 0; o < 4; o++) o4[o] += s * wr[o];
    }
#pragma unroll
    for (int o = 0; o < 4; o++) red[o][tid] = o4[o];
    __syncthreads();
    for (int st = 128; st > 0; st >>= 1) {
        if (tid < st)
#pragma unroll
            for (int o = 0; o < 4; o++) red[o][tid] += red[o][tid + st];
        __syncthreads();
    }
    if (tid < 4) out[b * 4 + tid] = red[tid][0];
}

// ================= launcher =================
extern "C" void kernel_launch(void* const* d_in, const int* in_sizes, int n_in,
                              void* d_out, int out_size) {
    const int*   src        = (const int*)d_in[0];
    const int*   wsrc       = (const int*)d_in[1];
    const float* char_table = (const float*)d_in[2];
    const float* word_table = (const float*)d_in[3];
    const float* w_bi  = (const float*)d_in[4];
    const float* b_bi  = (const float*)d_in[5];
    const float* w_tri = (const float*)d_in[6];
    const float* b_tri = (const float*)d_in[7];
    const float* Wa    = (const float*)d_in[8];
    const float* ba    = (const float*)d_in[9];
    const float* ua    = (const float*)d_in[10];
    const float* W1    = (const float*)d_in[11];
    const float* wih0  = (const float*)d_in[12];
    const float* whh0  = (const float*)d_in[13];
    const float* b0    = (const float*)d_in[14];
    const float* wih1  = (const float*)d_in[15];
    const float* whh1  = (const float*)d_in[16];
    const float* b1    = (const float*)d_in[17];
    const float* Wout  = (const float*)d_in[18];
    float* out = (float*)d_out;

#define SYMF(p, s) float* p; cudaGetSymbolAddress((void**)&p, s)
    SYMF(p_we, g_we); SYMF(p_feats, g_feats);
    SYMF(p_xg0, g_xg0); SYMF(p_xg1, g_xg1);
    SYMF(p_h0, g_h0); SYMF(p_h1, g_h1);
    SYMF(p_c, g_cst); SYMF(p_gates, g_gates);
    SYMF(p_W1T, g_W1T);

    // prep: packed conv weights, pe/W1T, char tables, folded attn tables
    prep_wcat_k<<<512, 256>>>(w_bi, b_bi, w_tri, b_tri);
    prep_misc_k<<<256, 256>>>(W1);
    tbl_k<<<384, 256>>>(char_table);
    ta_k<<<384, 256>>>(Wa);
    pb_k<<<20, 512>>>(Wa, ba);

    // NEW front-end: fused char-CNN + attention via tables -> we (fp32)
    scoreattn_k<<<8192, 256>>>(src, ua, p_we);

    // feats[:, :256] = we @ W1 (permuted rows -> [t][b]); feats[:, 256:] = word emb
    gemm_k<0, 3><<<dim3(2, 64, 1), 256>>>(
        p_we, 512, p_W1T, 512, 0, p_feats, 512, 0, nullptr, 0, 512,
        nullptr, nullptr, nullptr, nullptr, nullptr);
    wgather_k<<<8192, 64>>>(wsrc, word_table, p_feats);

    // xg0 = feats @ wih0^T + b0  (known-good FFMA, z = dir)
    gemm_k<0, 0><<<dim3(16, 64, 2), 256>>>(
        p_feats, 512, wih0, 512, (long long)2048 * 512, p_xg0, 2048,
        (long long)8192 * 2048, b0, 2048, 512,
        nullptr, nullptr, nullptr, nullptr, nullptr);

    // layer-0 recurrence (known-good)
    for (int s = 0; s < 128; s++) {
        lstm_gates_k<<<dim3(64, 1, 2), 256>>>(p_h0, whh0, p_xg0, p_gates, s);
        lstm_update_k<<<dim3(64, 1, 2), 256>>>(p_gates, p_c, p_h0, s);
    }

    // xg1 = h0 @ wih1^T + b1
    gemm_k<0, 0><<<dim3(16, 64, 2), 256>>>(
        p_h0, 1024, wih1, 1024, (long long)2048 * 1024, p_xg1, 2048,
        (long long)8192 * 2048, b1, 2048, 1024,
        nullptr, nullptr, nullptr, nullptr, nullptr);

    // layer-1 recurrence (known-good)
    for (int s = 0; s < 128; s++) {
        lstm_gates_k<<<dim3(64, 1, 2), 256>>>(p_h1, whh1, p_xg1, p_gates, s);
        lstm_update_k<<<dim3(64, 1, 2), 256>>>(p_gates, p_c, p_h1, s);
    }

    out_k<<<64, 256>>>(p_h1, Wout, out);
}